// round 2
// baseline (speedup 1.0000x reference)
#include <cuda_runtime.h>

#define BATCH 65536
#define XDIM  362
#define GS    19
#define BM    64

typedef unsigned long long u64;

// ---------------- scratch ----------------
__device__ float g_att[BATCH * 6];
__device__ int   g_ptr[BATCH];
__device__ int   g_cnt[3];
__device__ int   g_off[4];
__device__ int   g_cur[3];
__device__ int   g_rowlist[BATCH + BM];

// ---------------- smem layout (float indices) ----------------
#define ATT   0                 // 384
#define W1S   384               // 600
#define B1S   984               // 100
#define B2S   1084              // 400
#define B3S   1484              // 100
#define W4S   1584              // 600
#define B4S   2184              // 8
#define PRED  2192              // 384
#define H1T   2592              // 104*64 = 6656 (rows 100..103 zeroed)
#define WST   9248              // 2 x 2048 double-buffered weight stage
#define H2S   13344             // 512*68 = 34816 (h2 transposed, pad 68)
#define SMEM_FLOATS (13344 + 34816)
#define SMEM_BYTES  (SMEM_FLOATS * 4)

// ---------------- f32x2 helpers ----------------
__device__ __forceinline__ u64 pack2(float w) {
    u64 r; asm("mov.b64 %0, {%1,%1};" : "=l"(r) : "f"(w)); return r;
}
__device__ __forceinline__ void fma2(u64 &acc, u64 a, u64 b) {
    asm("fma.rn.f32x2 %0, %1, %2, %0;" : "+l"(acc) : "l"(a), "l"(b));
}
__device__ __forceinline__ float2 unpack2(u64 v) {
    float2 f; asm("mov.b64 {%0,%1}, %2;" : "=f"(f.x), "=f"(f.y) : "l"(v)); return f;
}
__device__ __forceinline__ int clampi(int v) { return min(max(v, 1), XDIM - 1); }

__device__ __forceinline__ bool find_tile(int t, int &a, int &pos0, int &nrows) {
    #pragma unroll
    for (int q = 0; q < 3; q++) {
        int cnt = g_cnt[q];
        int ta  = (cnt + BM - 1) >> 6;
        if (t < ta) { a = q; pos0 = g_off[q] + t * BM; nrows = min(BM, cnt - t * BM); return true; }
        t -= ta;
    }
    return false;
}

// ---------------- kernel 0: zero counters ----------------
__global__ void zero_k() {
    int t = threadIdx.x;
    if (t < 3) { g_cnt[t] = 0; g_cur[t] = 0; }
}

// ---------------- kernel 1: copy + argmax + gather + count ----------------
__global__ __launch_bounds__(256) void prep_k(const float* __restrict__ x,
                                              const int* __restrict__ act,
                                              float* __restrict__ out) {
    int warp = (blockIdx.x * blockDim.x + threadIdx.x) >> 5;
    int lane = threadIdx.x & 31;
    if (warp >= BATCH) return;

    const float2* xr  = (const float2*)(x + (size_t)warp * XDIM);
    float2*       orr = (float2*)(out + (size_t)warp * XDIM);

    float best = -3.4e38f; int bidx = 0;
    #pragma unroll 2
    for (int j = lane; j < XDIM / 2; j += 32) {
        float2 v = xr[j];
        orr[j] = v;
        if (v.x > best) { best = v.x; bidx = 2 * j; }
        if (v.y > best) { best = v.y; bidx = 2 * j + 1; }
    }
    #pragma unroll
    for (int off = 16; off; off >>= 1) {
        float ov = __shfl_down_sync(0xffffffffu, best, off);
        int   oi = __shfl_down_sync(0xffffffffu, bidx, off);
        if (ov > best || (ov == best && oi < bidx)) { best = ov; bidx = oi; }
    }
    int ptr = __shfl_sync(0xffffffffu, bidx, 0);

    if (lane == 0) {
        g_ptr[warp] = ptr;
        atomicAdd(&g_cnt[act[warp]], 1);
    }
    if (lane < 6) {
        int id = 0;
        if      (lane == 1) id = ptr;
        else if (lane == 2) id = clampi(ptr - GS);
        else if (lane == 3) id = clampi(ptr + GS);
        else if (lane == 4) id = clampi(ptr - 1);
        else if (lane == 5) id = clampi(ptr + 1);
        g_att[warp * 6 + lane] = x[(size_t)warp * XDIM + id];
    }
}

// ---------------- kernel 2: offsets ----------------
__global__ void scan_k() {
    g_off[0] = 0;
    g_off[1] = g_cnt[0];
    g_off[2] = g_cnt[0] + g_cnt[1];
    g_off[3] = g_cnt[0] + g_cnt[1] + g_cnt[2];
}

// ---------------- kernel 3: compact (warp-aggregated atomics) ----------------
__global__ __launch_bounds__(256) void compact_k(const int* __restrict__ act) {
    int r = blockIdx.x * blockDim.x + threadIdx.x;
    int lane = threadIdx.x & 31;
    int a = act[r];
    unsigned mask = __match_any_sync(0xffffffffu, a);
    int leader = __ffs(mask) - 1;
    int base = 0;
    if (lane == leader) base = atomicAdd(&g_cur[a], __popc(mask));
    base = __shfl_sync(0xffffffffu, base, leader);
    int pos = g_off[a] + base + __popc(mask & ((1u << lane) - 1u));
    g_rowlist[pos] = r;
}

// ---------------- kernel 4: fused MLP (L1+L2+L3+L4+scatter) ----------------
__global__ __launch_bounds__(256, 1) void fused_k(
        const float* __restrict__ W1, const float* __restrict__ b1,
        const float* __restrict__ W2, const float* __restrict__ b2,
        const float* __restrict__ W3, const float* __restrict__ b3,
        const float* __restrict__ W4, const float* __restrict__ b4,
        float* __restrict__ out) {
    extern __shared__ float sm[];

    int a, pos0, nrows;
    if (!find_tile(blockIdx.x, a, pos0, nrows)) return;
    int tid = threadIdx.x;
    int tx  = tid & 31, ty = tid >> 5;
    int r0  = ty * 8;

    // ---- phase A: load small operands ----
    for (int e = tid; e < 384; e += 256) {
        int i = e / 6;
        sm[ATT + e] = (i < nrows) ? g_att[g_rowlist[pos0 + i] * 6 + (e % 6)] : 0.f;
    }
    for (int e = tid; e < 600; e += 256) sm[W1S + e] = W1[a * 600 + e];
    for (int e = tid; e < 100; e += 256) sm[B1S + e] = b1[a * 100 + e];
    for (int e = tid; e < 400; e += 256) sm[B2S + e] = b2[a * 400 + e];
    for (int e = tid; e < 100; e += 256) sm[B3S + e] = b3[a * 100 + e];
    for (int e = tid; e < 600; e += 256) sm[W4S + e] = W4[a * 600 + e];
    if (tid < 6) sm[B4S + tid] = b4[a * 6 + tid];
    __syncthreads();

    // ---- L1: h1T[n][i] (104 rows, 100..103 zero pad) ----
    for (int e = tid; e < 104 * 64; e += 256) {
        int n = e >> 6, i = e & 63;
        float v = 0.f;
        if (n < 100) {
            v = sm[B1S + n];
            #pragma unroll
            for (int k = 0; k < 6; k++) v += sm[ATT + i * 6 + k] * sm[W1S + k * 100 + n];
            v = fmaxf(v, 0.f);
        }
        sm[H1T + n * 64 + i] = v;
    }

    const float* W2a = W2 + a * 40000;
    const float* W3a = W3 + a * 40000;
    int klp  = tid >> 5, n0  = (tid & 31) * 8;   // L2 staging map: 8x256 chunk
    int klp3 = tid >> 4, n03 = (tid & 15) * 8;   // L3 staging map: 16x128 chunk

    // ---- L2: [64 x 100] x [100 x 512pad] ----
    for (int pass = 0; pass < 2; pass++) {
        int c0 = pass * 256;
        u64 acc[4][8];
        #pragma unroll
        for (int p = 0; p < 4; p++)
            #pragma unroll
            for (int j = 0; j < 8; j++) acc[p][j] = 0ull;

        float4 v0, v1;
        // prefetch chunk 0
        {
            int kg = klp;
            v0 = make_float4(0.f, 0.f, 0.f, 0.f); v1 = v0;
            const float* p = W2a + kg * 400 + c0 + n0;
            if (c0 + n0     < 400) v0 = *(const float4*)p;
            if (c0 + n0 + 4 < 400) v1 = *(const float4*)(p + 4);
        }
        *(float4*)&sm[WST + klp * 256 + n0]     = v0;
        *(float4*)&sm[WST + klp * 256 + n0 + 4] = v1;
        __syncthreads();  // also publishes h1T

        for (int ch = 0; ch < 13; ch++) {
            bool more = (ch + 1 < 13);
            if (more) {
                int kg = (ch + 1) * 8 + klp;
                v0 = make_float4(0.f, 0.f, 0.f, 0.f); v1 = v0;
                if (kg < 100) {
                    const float* p = W2a + kg * 400 + c0 + n0;
                    if (c0 + n0     < 400) v0 = *(const float4*)p;
                    if (c0 + n0 + 4 < 400) v1 = *(const float4*)(p + 4);
                }
            }
            const float* Ws = &sm[WST + (ch & 1) * 2048];
            #pragma unroll
            for (int kl = 0; kl < 8; kl++) {
                int k = ch * 8 + kl;
                ulonglong2 aA = *(const ulonglong2*)&sm[H1T + k * 64 + r0];
                ulonglong2 aB = *(const ulonglong2*)&sm[H1T + k * 64 + r0 + 4];
                #pragma unroll
                for (int j = 0; j < 8; j++) {
                    u64 w = pack2(Ws[kl * 256 + j * 32 + tx]);
                    fma2(acc[0][j], aA.x, w);
                    fma2(acc[1][j], aA.y, w);
                    fma2(acc[2][j], aB.x, w);
                    fma2(acc[3][j], aB.y, w);
                }
            }
            if (more) {
                int b = ((ch + 1) & 1) * 2048;
                *(float4*)&sm[WST + b + klp * 256 + n0]     = v0;
                *(float4*)&sm[WST + b + klp * 256 + n0 + 4] = v1;
            }
            __syncthreads();
        }
        // epilogue: bias+relu -> h2T in smem (stride 68)
        #pragma unroll
        for (int j = 0; j < 8; j++) {
            int c = c0 + j * 32 + tx;
            if (c < 400) {
                float b = sm[B2S + c];
                #pragma unroll
                for (int rp = 0; rp < 4; rp++) {
                    float2 v = unpack2(acc[rp][j]);
                    *(float2*)&sm[H2S + c * 68 + r0 + 2 * rp] =
                        make_float2(fmaxf(v.x + b, 0.f), fmaxf(v.y + b, 0.f));
                }
            }
        }
    }

    // ---- L3: [64 x 400] x [400 x 128pad] ----
    {
        u64 acc[4][4];
        #pragma unroll
        for (int p = 0; p < 4; p++)
            #pragma unroll
            for (int j = 0; j < 4; j++) acc[p][j] = 0ull;

        float wb[8];
        // prefetch chunk 0
        {
            int kg = klp3;
            #pragma unroll
            for (int e = 0; e < 8; e++) {
                int n = n03 + e;
                wb[e] = (n < 100) ? W3a[kg * 100 + n] : 0.f;
            }
        }
        #pragma unroll
        for (int e = 0; e < 8; e++) sm[WST + klp3 * 128 + n03 + e] = wb[e];
        __syncthreads();  // also publishes h2T (all pass epilogues done)

        for (int ch = 0; ch < 25; ch++) {
            bool more = (ch + 1 < 25);
            if (more) {
                int kg = (ch + 1) * 16 + klp3;
                #pragma unroll
                for (int e = 0; e < 8; e++) {
                    int n = n03 + e;
                    wb[e] = (n < 100) ? W3a[kg * 100 + n] : 0.f;
                }
            }
            const float* Ws = &sm[WST + (ch & 1) * 2048];
            #pragma unroll
            for (int kl = 0; kl < 16; kl++) {
                int k = ch * 16 + kl;
                ulonglong2 aA = *(const ulonglong2*)&sm[H2S + k * 68 + r0];
                ulonglong2 aB = *(const ulonglong2*)&sm[H2S + k * 68 + r0 + 4];
                #pragma unroll
                for (int j = 0; j < 4; j++) {
                    u64 w = pack2(Ws[kl * 128 + j * 32 + tx]);
                    fma2(acc[0][j], aA.x, w);
                    fma2(acc[1][j], aA.y, w);
                    fma2(acc[2][j], aB.x, w);
                    fma2(acc[3][j], aB.y, w);
                }
            }
            if (more) {
                int b = ((ch + 1) & 1) * 2048;
                #pragma unroll
                for (int e = 0; e < 8; e++) sm[WST + b + klp3 * 128 + n03 + e] = wb[e];
            }
            __syncthreads();
        }
        // epilogue: h3 -> H2S rows [0,100) (stride 68), source rows fully consumed
        #pragma unroll
        for (int j = 0; j < 4; j++) {
            int n = j * 32 + tx;
            if (n < 100) {
                float b = sm[B3S + n];
                #pragma unroll
                for (int rp = 0; rp < 4; rp++) {
                    float2 v = unpack2(acc[rp][j]);
                    *(float2*)&sm[H2S + n * 68 + r0 + 2 * rp] =
                        make_float2(fmaxf(v.x + b, 0.f), fmaxf(v.y + b, 0.f));
                }
            }
        }
    }
    __syncthreads();

    // ---- L4: pred[r][m] = h3[r] . W4[:,m] + b4[m] ----
    for (int e = tid; e < BM * 6; e += 256) {
        int r = e / 6, m = e % 6;
        float s = sm[B4S + m];
        #pragma unroll 4
        for (int k = 0; k < 100; k++) s += sm[H2S + k * 68 + r] * sm[W4S + k * 6 + m];
        sm[PRED + e] = s;
    }
    __syncthreads();

    // ---- scatter: ordered stores, last j wins ----
    if (tid < nrows) {
        int row = g_rowlist[pos0 + tid];
        int ptr = g_ptr[row];
        float* orow = out + (size_t)row * XDIM;
        int idx[6];
        idx[0] = 0;
        idx[1] = ptr;
        idx[2] = clampi(ptr - GS);
        idx[3] = clampi(ptr + GS);
        idx[4] = clampi(ptr - 1);
        idx[5] = clampi(ptr + 1);
        #pragma unroll 1
        for (int j = 0; j < 6; j++)
            orow[idx[j]] = sm[ATT + tid * 6 + j] + sm[PRED + tid * 6 + j];
    }
}

// ---------------- launch ----------------
extern "C" void kernel_launch(void* const* d_in, const int* in_sizes, int n_in,
                              void* d_out, int out_size) {
    const float* x  = (const float*)d_in[0];
    const float* W1 = (const float*)d_in[1];
    const float* b1 = (const float*)d_in[2];
    const float* W2 = (const float*)d_in[3];
    const float* b2 = (const float*)d_in[4];
    const float* W3 = (const float*)d_in[5];
    const float* b3 = (const float*)d_in[6];
    const float* W4 = (const float*)d_in[7];
    const float* b4 = (const float*)d_in[8];
    const int*  act = (const int*)d_in[9];
    float* out = (float*)d_out;

    cudaFuncSetAttribute(fused_k, cudaFuncAttributeMaxDynamicSharedMemorySize, SMEM_BYTES);

    zero_k<<<1, 32>>>();
    prep_k<<<BATCH / 8, 256>>>(x, act, out);
    scan_k<<<1, 1>>>();
    compact_k<<<BATCH / 256, 256>>>(act);
    fused_k<<<BATCH / BM + 3, 256, SMEM_BYTES>>>(W1, b1, W2, b2, W3, b3, W4, b4, out);
}

// round 5
// speedup vs baseline: 1.0563x; 1.0563x over previous
#include <cuda_runtime.h>
#include <cstdint>

#define BATCH 65536
#define XDIM  362
#define GS    19
#define TM    128

// ---------------- scratch ----------------
__device__ float g_att[BATCH * 6];
__device__ int   g_ptr[BATCH];
__device__ int   g_cnt[3];
__device__ int   g_cur[3];
__device__ int   g_rowlist[BATCH + TM];

// ---------------- smem layout (float indices) ----------------
#define ATT   0        // 768  (128 x 6)
#define B2S   768      // 512  (padded to N2=512)
#define B3S   1280     // 104
#define W4S   1384     // 624  (104 x 6, k>=100 zero)
#define B4S   2008     // 8
#define W1S   2016     // 600
#define B1S   2616     // 104
#define PRED  2720     // 768
#define HS    3488     // 128*104 = 13312 : h1 (tf32), then W3 chunk [k128][n104]
#define W2S   16800    // 104*136 = 14144 : W2 chunk [k104][n128] stride 136; later h3s
#define H2S   30944    // 128*136 = 17408 : h2 chunk bounce (tf32)
#define SMEM_FLOATS 48352
#define SMEM_BYTES  (SMEM_FLOATS * 4)

// cvt.rna.tf32.f32 has a .b32 destination
__device__ __forceinline__ uint32_t to_tf32_u(float x) {
    uint32_t r; asm("cvt.rna.tf32.f32 %0, %1;" : "=r"(r) : "f"(x)); return r;
}
__device__ __forceinline__ float to_tf32_f(float x) {
    return __uint_as_float(to_tf32_u(x));
}
__device__ __forceinline__ void mma_tf32(float c[4], const uint32_t a[4],
                                         uint32_t b0, uint32_t b1) {
    asm volatile("mma.sync.aligned.m16n8k8.row.col.f32.tf32.tf32.f32 "
                 "{%0,%1,%2,%3}, {%4,%5,%6,%7}, {%8,%9}, {%0,%1,%2,%3};"
                 : "+f"(c[0]), "+f"(c[1]), "+f"(c[2]), "+f"(c[3])
                 : "r"(a[0]), "r"(a[1]), "r"(a[2]), "r"(a[3]), "r"(b0), "r"(b1));
}
__device__ __forceinline__ int clampi(int v) { return min(max(v, 1), XDIM - 1); }

// ---------------- kernel 0: zero ----------------
__global__ void zero_k() {
    int t = threadIdx.x;
    if (t < 3) { g_cnt[t] = 0; g_cur[t] = 0; }
}

// ---------------- kernel 1: copy + argmax + gather + count ----------------
__global__ __launch_bounds__(256) void prep_k(const float* __restrict__ x,
                                              const int* __restrict__ act,
                                              float* __restrict__ out) {
    int warp = (blockIdx.x * blockDim.x + threadIdx.x) >> 5;
    int lane = threadIdx.x & 31;
    if (warp >= BATCH) return;

    const float2* xr  = (const float2*)(x + (size_t)warp * XDIM);
    float2*       orr = (float2*)(out + (size_t)warp * XDIM);

    float best = -3.4e38f; int bidx = 0;
    #pragma unroll 2
    for (int j = lane; j < XDIM / 2; j += 32) {
        float2 v = xr[j];
        orr[j] = v;
        if (v.x > best) { best = v.x; bidx = 2 * j; }
        if (v.y > best) { best = v.y; bidx = 2 * j + 1; }
    }
    #pragma unroll
    for (int off = 16; off; off >>= 1) {
        float ov = __shfl_down_sync(0xffffffffu, best, off);
        int   oi = __shfl_down_sync(0xffffffffu, bidx, off);
        if (ov > best || (ov == best && oi < bidx)) { best = ov; bidx = oi; }
    }
    int ptr = __shfl_sync(0xffffffffu, bidx, 0);

    if (lane == 0) {
        g_ptr[warp] = ptr;
        atomicAdd(&g_cnt[act[warp]], 1);
    }
    if (lane < 6) {
        int id = 0;
        if      (lane == 1) id = ptr;
        else if (lane == 2) id = clampi(ptr - GS);
        else if (lane == 3) id = clampi(ptr + GS);
        else if (lane == 4) id = clampi(ptr - 1);
        else if (lane == 5) id = clampi(ptr + 1);
        g_att[warp * 6 + lane] = x[(size_t)warp * XDIM + id];
    }
}

// ---------------- kernel 2: compact ----------------
__global__ __launch_bounds__(256) void compact_k(const int* __restrict__ act) {
    int c0 = g_cnt[0], c1 = g_cnt[1];
    int r = blockIdx.x * blockDim.x + threadIdx.x;
    int lane = threadIdx.x & 31;
    int a = act[r];
    int off = (a == 0) ? 0 : (a == 1 ? c0 : c0 + c1);
    unsigned mask = __match_any_sync(0xffffffffu, a);
    int leader = __ffs(mask) - 1;
    int base = 0;
    if (lane == leader) base = atomicAdd(&g_cur[a], __popc(mask));
    base = __shfl_sync(0xffffffffu, base, leader);
    g_rowlist[off + base + __popc(mask & ((1u << lane) - 1u))] = r;
}

// ---------------- kernel 3: fused MLP with mma.sync tf32 ----------------
__global__ __launch_bounds__(256, 1) void fused_k(
        const float* __restrict__ W1, const float* __restrict__ b1,
        const float* __restrict__ W2, const float* __restrict__ b2,
        const float* __restrict__ W3, const float* __restrict__ b3,
        const float* __restrict__ W4, const float* __restrict__ b4,
        float* __restrict__ out) {
    extern __shared__ float sm[];

    // tile -> (action, pos0, nrows)
    int a = -1, pos0 = 0, nrows = 0;
    {
        int t = blockIdx.x, offs = 0;
        #pragma unroll
        for (int q = 0; q < 3; q++) {
            int cnt = g_cnt[q];
            int ta  = (cnt + TM - 1) >> 7;
            if (a < 0 && t < ta) { a = q; pos0 = offs + t * TM; nrows = min(TM, cnt - t * TM); }
            if (a < 0) t -= ta;
            offs += cnt;
        }
        if (a < 0) return;
    }

    int tid  = threadIdx.x;
    int lane = tid & 31;
    int g    = lane >> 2;       // groupID
    int t4   = lane & 3;        // threadID in group
    int w    = tid >> 5;
    int row0 = w * 16;

    // ---- stage small params + att ----
    for (int e = tid; e < 768; e += 256) {
        int i = e / 6;
        sm[ATT + e] = (i < nrows) ? g_att[g_rowlist[pos0 + i] * 6 + (e % 6)] : 0.f;
    }
    for (int e = tid; e < 512; e += 256) sm[B2S + e] = (e < 400) ? b2[a * 400 + e] : 0.f;
    if (tid < 104) sm[B3S + tid] = (tid < 100) ? b3[a * 100 + tid] : 0.f;
    for (int e = tid; e < 624; e += 256) {
        int k = e / 6;
        sm[W4S + e] = (k < 100) ? W4[a * 600 + e] : 0.f;
    }
    if (tid < 8) sm[B4S + tid] = (tid < 6) ? b4[a * 6 + tid] : 0.f;
    for (int e = tid; e < 600; e += 256) sm[W1S + e] = W1[a * 600 + e];
    if (tid < 104) sm[B1S + tid] = (tid < 100) ? b1[a * 100 + tid] : 0.f;
    __syncthreads();

    // ---- L1 (fp32 scalar) -> h1 tf32 in HS [128][104] ----
    {
        int r  = tid >> 1;
        int h0 = (tid & 1) * 52;
        float av[6];
        #pragma unroll
        for (int k = 0; k < 6; k++) av[k] = sm[ATT + r * 6 + k];
        for (int n = h0; n < h0 + 52; n++) {
            float v = 0.f;
            if (n < 100) {
                v = sm[B1S + n];
                #pragma unroll
                for (int k = 0; k < 6; k++) v += av[k] * sm[W1S + k * 100 + n];
                v = to_tf32_f(fmaxf(v, 0.f));
            }
            sm[HS + r * 104 + n] = v;
        }
    }
    __syncthreads();

    // ---- A2 fragments (h1) held in regs: m16 x k104 per warp ----
    uint32_t a2f[13][4];
    #pragma unroll
    for (int kk = 0; kk < 13; kk++) {
        int base = HS + (row0 + g) * 104 + kk * 8 + t4;
        a2f[kk][0] = __float_as_uint(sm[base]);
        a2f[kk][1] = __float_as_uint(sm[base + 8 * 104]);
        a2f[kk][2] = __float_as_uint(sm[base + 4]);
        a2f[kk][3] = __float_as_uint(sm[base + 8 * 104 + 4]);
    }

    const float* W2a = W2 + a * 40000;
    const float* W3a = W3 + a * 40000;

    float h3acc[13][4];
    #pragma unroll
    for (int nn = 0; nn < 13; nn++)
        #pragma unroll
        for (int j = 0; j < 4; j++) h3acc[nn][j] = 0.f;

    #pragma unroll 1
    for (int c = 0; c < 4; c++) {
        // ---- stage W2 chunk [k 0..103][n' 0..127], tf32, stride 136 ----
        #pragma unroll 1
        for (int e4 = tid; e4 < 104 * 32; e4 += 256) {
            int k = e4 >> 5, n4 = (e4 & 31) << 2;
            float4 v = make_float4(0.f, 0.f, 0.f, 0.f);
            if (k < 100 && c * 128 + n4 < 400) {
                v = *(const float4*)(W2a + k * 400 + c * 128 + n4);
                v.x = to_tf32_f(v.x); v.y = to_tf32_f(v.y);
                v.z = to_tf32_f(v.z); v.w = to_tf32_f(v.w);
            }
            *(float4*)&sm[W2S + k * 136 + n4] = v;
        }
        __syncthreads();

        // ---- L2 mma: h2 chunk [m16 x n128] per warp ----
        float hacc[16][4];
        #pragma unroll
        for (int nn = 0; nn < 16; nn++)
            #pragma unroll
            for (int j = 0; j < 4; j++) hacc[nn][j] = 0.f;

        #pragma unroll
        for (int kk = 0; kk < 13; kk++) {
            int brow = W2S + (kk * 8 + t4) * 136 + g;
            #pragma unroll
            for (int nn = 0; nn < 16; nn++) {
                uint32_t b0 = __float_as_uint(sm[brow + nn * 8]);
                uint32_t b1 = __float_as_uint(sm[brow + 4 * 136 + nn * 8]);
                mma_tf32(hacc[nn], a2f[kk], b0, b1);
            }
        }

        // ---- bounce: relu(h2+b2) tf32 -> H2S (warp-private rows) ----
        #pragma unroll
        for (int nn = 0; nn < 16; nn++) {
            int colL = nn * 8 + 2 * t4;
            int colG = c * 128 + colL;
            float bb0 = sm[B2S + colG], bb1 = sm[B2S + colG + 1];
            float2 v0 = make_float2(to_tf32_f(fmaxf(hacc[nn][0] + bb0, 0.f)),
                                    to_tf32_f(fmaxf(hacc[nn][1] + bb1, 0.f)));
            float2 v1 = make_float2(to_tf32_f(fmaxf(hacc[nn][2] + bb0, 0.f)),
                                    to_tf32_f(fmaxf(hacc[nn][3] + bb1, 0.f)));
            *(float2*)&sm[H2S + (row0 + g) * 136 + colL]     = v0;
            *(float2*)&sm[H2S + (row0 + g + 8) * 136 + colL] = v1;
        }
        __syncwarp();

        // ---- A3 fragments (h2 chunk): m16 x k128 ----
        uint32_t a3f[16][4];
        #pragma unroll
        for (int kk = 0; kk < 16; kk++) {
            int base = H2S + (row0 + g) * 136 + kk * 8 + t4;
            a3f[kk][0] = __float_as_uint(sm[base]);
            a3f[kk][1] = __float_as_uint(sm[base + 8 * 136]);
            a3f[kk][2] = __float_as_uint(sm[base + 4]);
            a3f[kk][3] = __float_as_uint(sm[base + 8 * 136 + 4]);
        }
        __syncthreads();

        // ---- stage W3 chunk into HS [k' 0..127][n 0..103] stride 104 ----
        #pragma unroll 1
        for (int e = tid; e < 128 * 104; e += 256) {
            int k = e / 104, n = e - k * 104;
            int kg = c * 128 + k;
            sm[HS + e] = (n < 100 && kg < 400) ? to_tf32_f(W3a[kg * 100 + n]) : 0.f;
        }
        __syncthreads();

        // ---- L3 mma: h3 += h2c @ W3c ----
        #pragma unroll
        for (int kk = 0; kk < 16; kk++) {
            int brow = HS + (kk * 8 + t4) * 104 + g;
            #pragma unroll
            for (int nn = 0; nn < 13; nn++) {
                uint32_t b0 = __float_as_uint(sm[brow + nn * 8]);
                uint32_t b1 = __float_as_uint(sm[brow + 4 * 104 + nn * 8]);
                mma_tf32(h3acc[nn], a3f[kk], b0, b1);
            }
        }
    }

    // ---- h3 epilogue: relu(h3+b3) -> h3s (reuse W2S region, stride 104) ----
    #pragma unroll
    for (int nn = 0; nn < 13; nn++) {
        int col = nn * 8 + 2 * t4;
        float bb0 = sm[B3S + col], bb1 = sm[B3S + col + 1];
        float2 v0 = make_float2(fmaxf(h3acc[nn][0] + bb0, 0.f),
                                fmaxf(h3acc[nn][1] + bb1, 0.f));
        float2 v1 = make_float2(fmaxf(h3acc[nn][2] + bb0, 0.f),
                                fmaxf(h3acc[nn][3] + bb1, 0.f));
        *(float2*)&sm[W2S + (row0 + g) * 104 + col]     = v0;
        *(float2*)&sm[W2S + (row0 + g + 8) * 104 + col] = v1;
    }
    __syncthreads();

    // ---- L4 (fp32 scalar): pred[r][m] ----
    for (int e = tid; e < 768; e += 256) {
        int r = e / 6, m = e % 6;
        float s = sm[B4S + m];
        #pragma unroll 4
        for (int k = 0; k < 100; k++) s += sm[W2S + r * 104 + k] * sm[W4S + k * 6 + m];
        sm[PRED + e] = s;
    }
    __syncthreads();

    // ---- scatter: ordered stores, last j wins ----
    if (tid < nrows) {
        int row = g_rowlist[pos0 + tid];
        int ptr = g_ptr[row];
        float* orow = out + (size_t)row * XDIM;
        int idx[6];
        idx[0] = 0;
        idx[1] = ptr;
        idx[2] = clampi(ptr - GS);
        idx[3] = clampi(ptr + GS);
        idx[4] = clampi(ptr - 1);
        idx[5] = clampi(ptr + 1);
        #pragma unroll 1
        for (int j = 0; j < 6; j++)
            orow[idx[j]] = sm[ATT + tid * 6 + j] + sm[PRED + tid * 6 + j];
    }
}

// ---------------- launch ----------------
extern "C" void kernel_launch(void* const* d_in, const int* in_sizes, int n_in,
                              void* d_out, int out_size) {
    const float* x  = (const float*)d_in[0];
    const float* W1 = (const float*)d_in[1];
    const float* b1 = (const float*)d_in[2];
    const float* W2 = (const float*)d_in[3];
    const float* b2 = (const float*)d_in[4];
    const float* W3 = (const float*)d_in[5];
    const float* b3 = (const float*)d_in[6];
    const float* W4 = (const float*)d_in[7];
    const float* b4 = (const float*)d_in[8];
    const int*  act = (const int*)d_in[9];
    float* out = (float*)d_out;

    cudaFuncSetAttribute(fused_k, cudaFuncAttributeMaxDynamicSharedMemorySize, SMEM_BYTES);

    zero_k<<<1, 32>>>();
    prep_k<<<BATCH / 8, 256>>>(x, act, out);
    compact_k<<<BATCH / 256, 256>>>(act);
    fused_k<<<BATCH / TM + 3, 256, SMEM_BYTES>>>(W1, b1, W2, b2, W3, b3, W4, b4, out);
}

// round 6
// speedup vs baseline: 1.0742x; 1.0169x over previous
#include <cuda_runtime.h>
#include <cstdint>

#define BATCH 65536
#define XDIM  362
#define GS    19
#define TM    128

// ---------------- scratch ----------------
__device__ float g_att[BATCH * 6];
__device__ int   g_ptr[BATCH];
__device__ int   g_cnt[3];
__device__ int   g_cur[3];
__device__ int   g_rowlist[BATCH + TM];

// ---------------- smem layout (float indices) ----------------
#define ATT   0        // 768  (128 x 6)
#define B2S   768      // 512
#define B3S   1280     // 104
#define B4S   1384     // 8
#define W1S   1392     // 600
#define B1S   1992     // 104
#define PRED  2096     // 768
#define W4B   2864     // 104*8 B-frag layout [k][8], tf32
#define HS    3696     // 128*104 = 13312 : h1 (tf32) [r][k] stride 104
#define W2S   17008    // 104*136 = 14144 : W2 chunk [k104][n128] stride 136
#define W3S   31152    // 128*136 = 17408 : W3 chunk [k128][n104] stride 136
#define SMEM_FLOATS 48560
#define SMEM_BYTES  (SMEM_FLOATS * 4)

// cvt.rna.tf32.f32 has a .b32 destination
__device__ __forceinline__ uint32_t to_tf32_u(float x) {
    uint32_t r; asm("cvt.rna.tf32.f32 %0, %1;" : "=r"(r) : "f"(x)); return r;
}
__device__ __forceinline__ float to_tf32_f(float x) {
    return __uint_as_float(to_tf32_u(x));
}
__device__ __forceinline__ void mma_tf32(float c[4], const uint32_t a[4],
                                         uint32_t b0, uint32_t b1) {
    asm volatile("mma.sync.aligned.m16n8k8.row.col.f32.tf32.tf32.f32 "
                 "{%0,%1,%2,%3}, {%4,%5,%6,%7}, {%8,%9}, {%0,%1,%2,%3};"
                 : "+f"(c[0]), "+f"(c[1]), "+f"(c[2]), "+f"(c[3])
                 : "r"(a[0]), "r"(a[1]), "r"(a[2]), "r"(a[3]), "r"(b0), "r"(b1));
}
__device__ __forceinline__ int clampi(int v) { return min(max(v, 1), XDIM - 1); }

// Convert epilogued C-fragment (m16n8, values c[4] already tf32) into the
// A-fragment (m16k8) of the next mma, entirely in registers.
__device__ __forceinline__ void cfrag_to_afrag(const float c[4], uint32_t f[4], int t4) {
    const unsigned FULL = 0xffffffffu;
    int lane = threadIdx.x & 31;
    int src0 = (lane & ~3) | (t4 >> 1);
    int src2 = src0 + 2;
    float x0 = __shfl_sync(FULL, c[0], src0);
    float x1 = __shfl_sync(FULL, c[1], src0);
    float y0 = __shfl_sync(FULL, c[0], src2);
    float y1 = __shfl_sync(FULL, c[1], src2);
    f[0] = __float_as_uint((t4 & 1) ? x1 : x0);
    f[2] = __float_as_uint((t4 & 1) ? y1 : y0);
    x0 = __shfl_sync(FULL, c[2], src0);
    x1 = __shfl_sync(FULL, c[3], src0);
    y0 = __shfl_sync(FULL, c[2], src2);
    y1 = __shfl_sync(FULL, c[3], src2);
    f[1] = __float_as_uint((t4 & 1) ? x1 : x0);
    f[3] = __float_as_uint((t4 & 1) ? y1 : y0);
}

// ---------------- kernel 0: zero ----------------
__global__ void zero_k() {
    int t = threadIdx.x;
    if (t < 3) { g_cnt[t] = 0; g_cur[t] = 0; }
}

// ---------------- kernel 1: copy + argmax + gather + count ----------------
__global__ __launch_bounds__(256) void prep_k(const float* __restrict__ x,
                                              const int* __restrict__ act,
                                              float* __restrict__ out) {
    int warp = (blockIdx.x * blockDim.x + threadIdx.x) >> 5;
    int lane = threadIdx.x & 31;
    if (warp >= BATCH) return;

    const float2* xr  = (const float2*)(x + (size_t)warp * XDIM);
    float2*       orr = (float2*)(out + (size_t)warp * XDIM);

    float best = -3.4e38f; int bidx = 0;
    #pragma unroll 2
    for (int j = lane; j < XDIM / 2; j += 32) {
        float2 v = xr[j];
        orr[j] = v;
        if (v.x > best) { best = v.x; bidx = 2 * j; }
        if (v.y > best) { best = v.y; bidx = 2 * j + 1; }
    }
    #pragma unroll
    for (int off = 16; off; off >>= 1) {
        float ov = __shfl_down_sync(0xffffffffu, best, off);
        int   oi = __shfl_down_sync(0xffffffffu, bidx, off);
        if (ov > best || (ov == best && oi < bidx)) { best = ov; bidx = oi; }
    }
    int ptr = __shfl_sync(0xffffffffu, bidx, 0);

    if (lane == 0) {
        g_ptr[warp] = ptr;
        atomicAdd(&g_cnt[act[warp]], 1);
    }
    if (lane < 6) {
        int id = 0;
        if      (lane == 1) id = ptr;
        else if (lane == 2) id = clampi(ptr - GS);
        else if (lane == 3) id = clampi(ptr + GS);
        else if (lane == 4) id = clampi(ptr - 1);
        else if (lane == 5) id = clampi(ptr + 1);
        g_att[warp * 6 + lane] = x[(size_t)warp * XDIM + id];
    }
}

// ---------------- kernel 2: compact ----------------
__global__ __launch_bounds__(256) void compact_k(const int* __restrict__ act) {
    int c0 = g_cnt[0], c1 = g_cnt[1];
    int r = blockIdx.x * blockDim.x + threadIdx.x;
    int lane = threadIdx.x & 31;
    int a = act[r];
    int off = (a == 0) ? 0 : (a == 1 ? c0 : c0 + c1);
    unsigned mask = __match_any_sync(0xffffffffu, a);
    int leader = __ffs(mask) - 1;
    int base = 0;
    if (lane == leader) base = atomicAdd(&g_cur[a], __popc(mask));
    base = __shfl_sync(0xffffffffu, base, leader);
    g_rowlist[off + base + __popc(mask & ((1u << lane) - 1u))] = r;
}

// ---------------- kernel 3: fused MLP, register-resident L2->L3->L4 ----------------
__global__ __launch_bounds__(256, 1) void fused_k(
        const float* __restrict__ W1, const float* __restrict__ b1,
        const float* __restrict__ W2, const float* __restrict__ b2,
        const float* __restrict__ W3, const float* __restrict__ b3,
        const float* __restrict__ W4, const float* __restrict__ b4,
        float* __restrict__ out) {
    extern __shared__ float sm[];

    // tile -> (action, pos0, nrows)
    int a = -1, pos0 = 0, nrows = 0;
    {
        int t = blockIdx.x, offs = 0;
        #pragma unroll
        for (int q = 0; q < 3; q++) {
            int cnt = g_cnt[q];
            int ta  = (cnt + TM - 1) >> 7;
            if (a < 0 && t < ta) { a = q; pos0 = offs + t * TM; nrows = min(TM, cnt - t * TM); }
            if (a < 0) t -= ta;
            offs += cnt;
        }
        if (a < 0) return;
    }

    int tid  = threadIdx.x;
    int lane = tid & 31;
    int g    = lane >> 2;       // groupID
    int t4   = lane & 3;        // threadID in group
    int w    = tid >> 5;
    int row0 = w * 16;

    // ---- stage small params + att ----
    for (int e = tid; e < 768; e += 256) {
        int i = e / 6;
        sm[ATT + e] = (i < nrows) ? g_att[g_rowlist[pos0 + i] * 6 + (e % 6)] : 0.f;
    }
    for (int e = tid; e < 512; e += 256) sm[B2S + e] = (e < 400) ? b2[a * 400 + e] : 0.f;
    if (tid < 104) sm[B3S + tid] = (tid < 100) ? b3[a * 100 + tid] : 0.f;
    if (tid < 8)   sm[B4S + tid] = (tid < 6) ? b4[a * 6 + tid] : 0.f;
    for (int e = tid; e < 600; e += 256) sm[W1S + e] = W1[a * 600 + e];
    if (tid < 104) sm[B1S + tid] = (tid < 100) ? b1[a * 100 + tid] : 0.f;
    // W4 B-fragment layout: [k pad 104][n pad 8], tf32
    for (int e = tid; e < 832; e += 256) {
        int k = e >> 3, n = e & 7;
        sm[W4B + e] = (k < 100 && n < 6) ? to_tf32_f(W4[a * 600 + k * 6 + n]) : 0.f;
    }
    __syncthreads();

    // ---- L1 (fp32 scalar) -> h1 tf32 in HS [128][104] ----
    {
        int r  = tid >> 1;
        int h0 = (tid & 1) * 52;
        float av[6];
        #pragma unroll
        for (int k = 0; k < 6; k++) av[k] = sm[ATT + r * 6 + k];
        for (int n = h0; n < h0 + 52; n++) {
            float v = 0.f;
            if (n < 100) {
                v = sm[B1S + n];
                #pragma unroll
                for (int k = 0; k < 6; k++) v += av[k] * sm[W1S + k * 100 + n];
                v = to_tf32_f(fmaxf(v, 0.f));
            }
            sm[HS + r * 104 + n] = v;
        }
    }
    __syncthreads();

    // ---- A2 fragments (h1): m16 x k104 per warp, held in regs ----
    uint32_t a2f[13][4];
    #pragma unroll
    for (int kk = 0; kk < 13; kk++) {
        int base = HS + (row0 + g) * 104 + kk * 8 + t4;
        a2f[kk][0] = __float_as_uint(sm[base]);
        a2f[kk][1] = __float_as_uint(sm[base + 8 * 104]);
        a2f[kk][2] = __float_as_uint(sm[base + 4]);
        a2f[kk][3] = __float_as_uint(sm[base + 8 * 104 + 4]);
    }

    const float* W2a = W2 + a * 40000;
    const float* W3a = W3 + a * 40000;

    float h3acc[13][4];
    #pragma unroll
    for (int j = 0; j < 13; j++)
        #pragma unroll
        for (int i = 0; i < 4; i++) h3acc[j][i] = 0.f;

    #pragma unroll 1
    for (int c = 0; c < 4; c++) {
        __syncthreads();   // previous chunk's mma fully consumed W2S/W3S

        // ---- stage W2 chunk [k 0..103][n' 0..127], tf32, stride 136 ----
        #pragma unroll 1
        for (int e4 = tid; e4 < 104 * 32; e4 += 256) {
            int k = e4 >> 5, n4 = (e4 & 31) << 2;
            float4 v = make_float4(0.f, 0.f, 0.f, 0.f);
            if (k < 100 && c * 128 + n4 < 400) {
                v = *(const float4*)(W2a + k * 400 + c * 128 + n4);
                v.x = to_tf32_f(v.x); v.y = to_tf32_f(v.y);
                v.z = to_tf32_f(v.z); v.w = to_tf32_f(v.w);
            }
            *(float4*)&sm[W2S + k * 136 + n4] = v;
        }
        // ---- stage W3 chunk [k' 0..127][n 0..103], tf32, stride 136 ----
        #pragma unroll 1
        for (int e = tid; e < 128 * 104; e += 256) {
            int k = e / 104, n = e - k * 104;
            int kg = c * 128 + k;
            sm[W3S + k * 136 + n] = (n < 100 && kg < 400) ? to_tf32_f(W3a[kg * 100 + n]) : 0.f;
        }
        __syncthreads();

        // ---- paired n-blocks: L2 mma -> epilogue -> shuffle -> L3 mma ----
        #pragma unroll 1
        for (int pp = 0; pp < 8; pp++) {
            int nn0 = 2 * pp, nn1 = 2 * pp + 1;
            float h0[4] = {0.f, 0.f, 0.f, 0.f};
            float h1v[4] = {0.f, 0.f, 0.f, 0.f};

            #pragma unroll
            for (int kk = 0; kk < 13; kk++) {
                int brow = W2S + (kk * 8 + t4) * 136 + g;
                uint32_t b00 = __float_as_uint(sm[brow + nn0 * 8]);
                uint32_t b01 = __float_as_uint(sm[brow + 4 * 136 + nn0 * 8]);
                uint32_t b10 = __float_as_uint(sm[brow + nn1 * 8]);
                uint32_t b11 = __float_as_uint(sm[brow + 4 * 136 + nn1 * 8]);
                mma_tf32(h0,  a2f[kk], b00, b01);
                mma_tf32(h1v, a2f[kk], b10, b11);
            }

            // epilogue (bias + relu + tf32) in C layout, then shuffle to A-frags
            uint32_t f0[4], f1[4];
            {
                int c00 = c * 128 + nn0 * 8 + 2 * t4;
                float ba = sm[B2S + c00], bb = sm[B2S + c00 + 1];
                float e0[4];
                e0[0] = to_tf32_f(fmaxf(h0[0] + ba, 0.f));
                e0[1] = to_tf32_f(fmaxf(h0[1] + bb, 0.f));
                e0[2] = to_tf32_f(fmaxf(h0[2] + ba, 0.f));
                e0[3] = to_tf32_f(fmaxf(h0[3] + bb, 0.f));
                cfrag_to_afrag(e0, f0, t4);
                int c10 = c * 128 + nn1 * 8 + 2 * t4;
                ba = sm[B2S + c10]; bb = sm[B2S + c10 + 1];
                e0[0] = to_tf32_f(fmaxf(h1v[0] + ba, 0.f));
                e0[1] = to_tf32_f(fmaxf(h1v[1] + bb, 0.f));
                e0[2] = to_tf32_f(fmaxf(h1v[2] + ba, 0.f));
                e0[3] = to_tf32_f(fmaxf(h1v[3] + bb, 0.f));
                cfrag_to_afrag(e0, f1, t4);
            }

            // L3: h3acc[j] += h2block(nn0) @ W3 + h2block(nn1) @ W3
            #pragma unroll
            for (int j = 0; j < 13; j++) {
                int br0 = W3S + (nn0 * 8 + t4) * 136 + g + j * 8;
                uint32_t b00 = __float_as_uint(sm[br0]);
                uint32_t b01 = __float_as_uint(sm[br0 + 4 * 136]);
                mma_tf32(h3acc[j], f0, b00, b01);
                int br1 = W3S + (nn1 * 8 + t4) * 136 + g + j * 8;
                uint32_t b10 = __float_as_uint(sm[br1]);
                uint32_t b11 = __float_as_uint(sm[br1 + 4 * 136]);
                mma_tf32(h3acc[j], f1, b10, b11);
            }
        }
    }

    // ---- L4 via mma: pred = relu(h3 + b3) @ W4 ----
    float h4[4] = {0.f, 0.f, 0.f, 0.f};
    #pragma unroll
    for (int j = 0; j < 13; j++) {
        int col = j * 8 + 2 * t4;
        float ba = sm[B3S + col], bb = sm[B3S + col + 1];
        float e0[4];
        e0[0] = to_tf32_f(fmaxf(h3acc[j][0] + ba, 0.f));
        e0[1] = to_tf32_f(fmaxf(h3acc[j][1] + bb, 0.f));
        e0[2] = to_tf32_f(fmaxf(h3acc[j][2] + ba, 0.f));
        e0[3] = to_tf32_f(fmaxf(h3acc[j][3] + bb, 0.f));
        uint32_t f[4];
        cfrag_to_afrag(e0, f, t4);
        uint32_t b0 = __float_as_uint(sm[W4B + (j * 8 + t4) * 8 + g]);
        uint32_t b1 = __float_as_uint(sm[W4B + (j * 8 + t4 + 4) * 8 + g]);
        mma_tf32(h4, f, b0, b1);
    }
    // write pred (cols 0..5 valid)
    {
        int m0 = 2 * t4;
        if (m0 < 6) {
            sm[PRED + (row0 + g) * 6 + m0]     = h4[0] + sm[B4S + m0];
            sm[PRED + (row0 + g + 8) * 6 + m0] = h4[2] + sm[B4S + m0];
            sm[PRED + (row0 + g) * 6 + m0 + 1]     = h4[1] + sm[B4S + m0 + 1];
            sm[PRED + (row0 + g + 8) * 6 + m0 + 1] = h4[3] + sm[B4S + m0 + 1];
        }
    }
    __syncthreads();

    // ---- scatter: ordered stores, last j wins ----
    if (tid < nrows) {
        int row = g_rowlist[pos0 + tid];
        int ptr = g_ptr[row];
        float* orow = out + (size_t)row * XDIM;
        int idx[6];
        idx[0] = 0;
        idx[1] = ptr;
        idx[2] = clampi(ptr - GS);
        idx[3] = clampi(ptr + GS);
        idx[4] = clampi(ptr - 1);
        idx[5] = clampi(ptr + 1);
        #pragma unroll 1
        for (int j = 0; j < 6; j++)
            orow[idx[j]] = sm[ATT + tid * 6 + j] + sm[PRED + tid * 6 + j];
    }
}

// ---------------- launch ----------------
extern "C" void kernel_launch(void* const* d_in, const int* in_sizes, int n_in,
                              void* d_out, int out_size) {
    const float* x  = (const float*)d_in[0];
    const float* W1 = (const float*)d_in[1];
    const float* b1 = (const float*)d_in[2];
    const float* W2 = (const float*)d_in[3];
    const float* b2 = (const float*)d_in[4];
    const float* W3 = (const float*)d_in[5];
    const float* b3 = (const float*)d_in[6];
    const float* W4 = (const float*)d_in[7];
    const float* b4 = (const float*)d_in[8];
    const int*  act = (const int*)d_in[9];
    float* out = (float*)d_out;

    cudaFuncSetAttribute(fused_k, cudaFuncAttributeMaxDynamicSharedMemorySize, SMEM_BYTES);

    zero_k<<<1, 32>>>();
    prep_k<<<BATCH / 8, 256>>>(x, act, out);
    compact_k<<<BATCH / 256, 256>>>(act);
    fused_k<<<BATCH / TM + 3, 256, SMEM_BYTES>>>(W1, b1, W2, b2, W3, b3, W4, b4, out);
}

// round 8
// speedup vs baseline: 2.4477x; 2.2787x over previous
// Resubmission of round-7 kernel — previous bench attempt failed with a
// broker-side container error before compile/run; theory untested.
#include <cuda_runtime.h>
#include <cstdint>

#define BATCH 65536
#define XDIM  362
#define GS    19
#define TM    128

// ---------------- scratch ----------------
__device__ float g_att[BATCH * 6];
__device__ int   g_ptr[BATCH];
__device__ int   g_cnt[3];
__device__ int   g_cur[3];
__device__ int   g_rowlist[BATCH + TM];

// ---------------- smem layout (float indices) ----------------
#define ATT   0        // 768  (128 x 6)
#define B2S   768      // 512
#define B3S   1280     // 104
#define B4S   1384     // 8
#define W1S   1392     // 600
#define B1S   1992     // 104
#define PRED  2096     // 768
#define W4B   2864     // 104*8 B-frag layout [k][8], tf32
#define HS    3696     // 128*104 = 13312 : h1 (tf32) [r][k] stride 104
#define W2S   17008    // 104*136 = 14144 : W2 chunk [k104][n128] stride 136
#define W3S   31152    // 128*136 = 17408 : W3 chunk [k128][n104] stride 136
#define SMEM_FLOATS 48560
#define SMEM_BYTES  (SMEM_FLOATS * 4)

// cvt.rna.tf32.f32 has a .b32 destination
__device__ __forceinline__ uint32_t to_tf32_u(float x) {
    uint32_t r; asm("cvt.rna.tf32.f32 %0, %1;" : "=r"(r) : "f"(x)); return r;
}
__device__ __forceinline__ float to_tf32_f(float x) {
    return __uint_as_float(to_tf32_u(x));
}
__device__ __forceinline__ void mma_tf32(float c[4], const uint32_t a[4],
                                         uint32_t b0, uint32_t b1) {
    asm volatile("mma.sync.aligned.m16n8k8.row.col.f32.tf32.tf32.f32 "
                 "{%0,%1,%2,%3}, {%4,%5,%6,%7}, {%8,%9}, {%0,%1,%2,%3};"
                 : "+f"(c[0]), "+f"(c[1]), "+f"(c[2]), "+f"(c[3])
                 : "r"(a[0]), "r"(a[1]), "r"(a[2]), "r"(a[3]), "r"(b0), "r"(b1));
}
__device__ __forceinline__ void cp16(uint32_t dst, const void* src) {
    asm volatile("cp.async.cg.shared.global [%0], [%1], 16;" :: "r"(dst), "l"(src));
}
__device__ __forceinline__ int clampi(int v) { return min(max(v, 1), XDIM - 1); }

// C-fragment (m16n8, tf32 values) -> A-fragment (m16k8) of next mma, in registers.
__device__ __forceinline__ void cfrag_to_afrag(const float c[4], uint32_t f[4], int t4) {
    const unsigned FULL = 0xffffffffu;
    int lane = threadIdx.x & 31;
    int src0 = (lane & ~3) | (t4 >> 1);
    int src2 = src0 + 2;
    float x0 = __shfl_sync(FULL, c[0], src0);
    float x1 = __shfl_sync(FULL, c[1], src0);
    float y0 = __shfl_sync(FULL, c[0], src2);
    float y1 = __shfl_sync(FULL, c[1], src2);
    f[0] = __float_as_uint((t4 & 1) ? x1 : x0);
    f[2] = __float_as_uint((t4 & 1) ? y1 : y0);
    x0 = __shfl_sync(FULL, c[2], src0);
    x1 = __shfl_sync(FULL, c[3], src0);
    y0 = __shfl_sync(FULL, c[2], src2);
    y1 = __shfl_sync(FULL, c[3], src2);
    f[1] = __float_as_uint((t4 & 1) ? x1 : x0);
    f[3] = __float_as_uint((t4 & 1) ? y1 : y0);
}

// ---------------- kernel 0: zero ----------------
__global__ void zero_k() {
    int t = threadIdx.x;
    if (t < 3) { g_cnt[t] = 0; g_cur[t] = 0; }
}

// ---------------- kernel 1: copy + argmax + gather + count ----------------
__global__ __launch_bounds__(256) void prep_k(const float* __restrict__ x,
                                              const int* __restrict__ act,
                                              float* __restrict__ out) {
    int warp = (blockIdx.x * blockDim.x + threadIdx.x) >> 5;
    int lane = threadIdx.x & 31;
    if (warp >= BATCH) return;

    const float2* xr  = (const float2*)(x + (size_t)warp * XDIM);
    float2*       orr = (float2*)(out + (size_t)warp * XDIM);

    float best = -3.4e38f; int bidx = 0;
    #pragma unroll 2
    for (int j = lane; j < XDIM / 2; j += 32) {
        float2 v = xr[j];
        orr[j] = v;
        if (v.x > best) { best = v.x; bidx = 2 * j; }
        if (v.y > best) { best = v.y; bidx = 2 * j + 1; }
    }
    #pragma unroll
    for (int off = 16; off; off >>= 1) {
        float ov = __shfl_down_sync(0xffffffffu, best, off);
        int   oi = __shfl_down_sync(0xffffffffu, bidx, off);
        if (ov > best || (ov == best && oi < bidx)) { best = ov; bidx = oi; }
    }
    int ptr = __shfl_sync(0xffffffffu, bidx, 0);

    if (lane == 0) {
        g_ptr[warp] = ptr;
        atomicAdd(&g_cnt[act[warp]], 1);
    }
    if (lane < 6) {
        int id = 0;
        if      (lane == 1) id = ptr;
        else if (lane == 2) id = clampi(ptr - GS);
        else if (lane == 3) id = clampi(ptr + GS);
        else if (lane == 4) id = clampi(ptr - 1);
        else if (lane == 5) id = clampi(ptr + 1);
        g_att[warp * 6 + lane] = x[(size_t)warp * XDIM + id];
    }
}

// ---------------- kernel 2: compact ----------------
__global__ __launch_bounds__(256) void compact_k(const int* __restrict__ act) {
    int c0 = g_cnt[0], c1 = g_cnt[1];
    int r = blockIdx.x * blockDim.x + threadIdx.x;
    int lane = threadIdx.x & 31;
    int a = act[r];
    int off = (a == 0) ? 0 : (a == 1 ? c0 : c0 + c1);
    unsigned mask = __match_any_sync(0xffffffffu, a);
    int leader = __ffs(mask) - 1;
    int base = 0;
    if (lane == leader) base = atomicAdd(&g_cur[a], __popc(mask));
    base = __shfl_sync(0xffffffffu, base, leader);
    g_rowlist[off + base + __popc(mask & ((1u << lane) - 1u))] = r;
}

// ---------------- kernel 3: fused MLP, quad-ILP mma + cp.async staging ----------------
__global__ __launch_bounds__(256, 1) void fused_k(
        const float* __restrict__ W1, const float* __restrict__ b1,
        const float* __restrict__ W2, const float* __restrict__ b2,
        const float* __restrict__ W3, const float* __restrict__ b3,
        const float* __restrict__ W4, const float* __restrict__ b4,
        float* __restrict__ out) {
    extern __shared__ float sm[];

    // tile -> (action, pos0, nrows)
    int a = -1, pos0 = 0, nrows = 0;
    {
        int t = blockIdx.x, offs = 0;
        #pragma unroll
        for (int q = 0; q < 3; q++) {
            int cnt = g_cnt[q];
            int ta  = (cnt + TM - 1) >> 7;
            if (a < 0 && t < ta) { a = q; pos0 = offs + t * TM; nrows = min(TM, cnt - t * TM); }
            if (a < 0) t -= ta;
            offs += cnt;
        }
        if (a < 0) return;
    }

    int tid  = threadIdx.x;
    int lane = tid & 31;
    int g    = lane >> 2;       // groupID
    int t4   = lane & 3;        // threadID in group
    int w    = tid >> 5;
    int row0 = w * 16;
    uint32_t smb = (uint32_t)__cvta_generic_to_shared(sm);

    const float* W2a = W2 + a * 40000;
    const float* W3a = W3 + a * 40000;

    // ---- async prefetch of chunk 0 weights (overlaps L1 below) ----
    {
        const int cc = 0;
        for (int e4 = tid; e4 < 104 * 32; e4 += 256) {
            int k = e4 >> 5, n4 = (e4 & 31) << 2;
            if (k < 100 && cc * 128 + n4 < 400)
                cp16(smb + (uint32_t)((W2S + k * 136 + n4) * 4), W2a + k * 400 + cc * 128 + n4);
            else
                *(float4*)&sm[W2S + k * 136 + n4] = make_float4(0.f, 0.f, 0.f, 0.f);
        }
        for (int e4 = tid; e4 < 128 * 26; e4 += 256) {
            int k = e4 / 26, u = e4 - k * 26;
            int n4 = u * 4, kg = cc * 128 + k;
            if (u < 25 && kg < 400)
                cp16(smb + (uint32_t)((W3S + k * 136 + n4) * 4), W3a + kg * 100 + n4);
            else
                *(float4*)&sm[W3S + k * 136 + n4] = make_float4(0.f, 0.f, 0.f, 0.f);
        }
        asm volatile("cp.async.commit_group;");
    }

    // ---- stage small params + att ----
    for (int e = tid; e < 768; e += 256) {
        int i = e / 6;
        sm[ATT + e] = (i < nrows) ? g_att[g_rowlist[pos0 + i] * 6 + (e % 6)] : 0.f;
    }
    for (int e = tid; e < 512; e += 256) sm[B2S + e] = (e < 400) ? b2[a * 400 + e] : 0.f;
    if (tid < 104) sm[B3S + tid] = (tid < 100) ? b3[a * 100 + tid] : 0.f;
    if (tid < 8)   sm[B4S + tid] = (tid < 6) ? b4[a * 6 + tid] : 0.f;
    for (int e = tid; e < 600; e += 256) sm[W1S + e] = W1[a * 600 + e];
    if (tid < 104) sm[B1S + tid] = (tid < 100) ? b1[a * 100 + tid] : 0.f;
    for (int e = tid; e < 832; e += 256) {
        int k = e >> 3, n = e & 7;
        sm[W4B + e] = (k < 100 && n < 6) ? to_tf32_f(W4[a * 600 + k * 6 + n]) : 0.f;
    }
    __syncthreads();

    // ---- L1 (fp32 scalar) -> h1 tf32 in HS [128][104] ----
    {
        int r  = tid >> 1;
        int h0 = (tid & 1) * 52;
        float av[6];
        #pragma unroll
        for (int k = 0; k < 6; k++) av[k] = sm[ATT + r * 6 + k];
        for (int n = h0; n < h0 + 52; n++) {
            float v = 0.f;
            if (n < 100) {
                v = sm[B1S + n];
                #pragma unroll
                for (int k = 0; k < 6; k++) v += av[k] * sm[W1S + k * 100 + n];
                v = to_tf32_f(fmaxf(v, 0.f));
            }
            sm[HS + r * 104 + n] = v;
        }
    }
    __syncthreads();

    // ---- A2 fragments (h1): m16 x k104 per warp, in regs ----
    uint32_t a2f[13][4];
    #pragma unroll
    for (int kk = 0; kk < 13; kk++) {
        int base = HS + (row0 + g) * 104 + kk * 8 + t4;
        a2f[kk][0] = __float_as_uint(sm[base]);
        a2f[kk][1] = __float_as_uint(sm[base + 8 * 104]);
        a2f[kk][2] = __float_as_uint(sm[base + 4]);
        a2f[kk][3] = __float_as_uint(sm[base + 8 * 104 + 4]);
    }

    float h3acc[13][4];
    #pragma unroll
    for (int j = 0; j < 13; j++)
        #pragma unroll
        for (int i = 0; i < 4; i++) h3acc[j][i] = 0.f;

    // chunk 0 weights must have landed
    asm volatile("cp.async.wait_group 0;" ::: "memory");
    __syncthreads();

    #pragma unroll 1
    for (int c = 0; c < 4; c++) {
        // ---- quads of n-blocks: L2 mma (4 chains) -> epilogue -> L3 mma ----
        #pragma unroll 1
        for (int qq = 0; qq < 4; qq++) {
            float h[4][4];
            #pragma unroll
            for (int q = 0; q < 4; q++)
                #pragma unroll
                for (int i = 0; i < 4; i++) h[q][i] = 0.f;

            #pragma unroll
            for (int kk = 0; kk < 13; kk++) {
                int brow = W2S + (kk * 8 + t4) * 136 + g;
                #pragma unroll
                for (int q = 0; q < 4; q++) {
                    int nb = qq * 4 + q;
                    uint32_t b0 = __float_as_uint(sm[brow + nb * 8]);
                    uint32_t b1 = __float_as_uint(sm[brow + 4 * 136 + nb * 8]);
                    mma_tf32(h[q], a2f[kk], b0, b1);
                }
            }

            uint32_t f[4][4];
            #pragma unroll
            for (int q = 0; q < 4; q++) {
                int nb = qq * 4 + q;
                int c00 = c * 128 + nb * 8 + 2 * t4;
                float ba = sm[B2S + c00], bb = sm[B2S + c00 + 1];
                float e0[4];
                e0[0] = to_tf32_f(fmaxf(h[q][0] + ba, 0.f));
                e0[1] = to_tf32_f(fmaxf(h[q][1] + bb, 0.f));
                e0[2] = to_tf32_f(fmaxf(h[q][2] + ba, 0.f));
                e0[3] = to_tf32_f(fmaxf(h[q][3] + bb, 0.f));
                cfrag_to_afrag(e0, f[q], t4);
            }

            #pragma unroll
            for (int q = 0; q < 4; q++) {
                int nb = qq * 4 + q;
                #pragma unroll
                for (int j = 0; j < 13; j++) {
                    int br = W3S + (nb * 8 + t4) * 136 + g + j * 8;
                    uint32_t b0 = __float_as_uint(sm[br]);
                    uint32_t b1 = __float_as_uint(sm[br + 4 * 136]);
                    mma_tf32(h3acc[j], f[q], b0, b1);
                }
            }
        }

        // ---- stage next chunk's weights ----
        if (c < 3) {
            const int cc = c + 1;
            __syncthreads();    // all warps done reading current chunk
            for (int e4 = tid; e4 < 104 * 32; e4 += 256) {
                int k = e4 >> 5, n4 = (e4 & 31) << 2;
                if (k < 100 && cc * 128 + n4 < 400)
                    cp16(smb + (uint32_t)((W2S + k * 136 + n4) * 4), W2a + k * 400 + cc * 128 + n4);
                else
                    *(float4*)&sm[W2S + k * 136 + n4] = make_float4(0.f, 0.f, 0.f, 0.f);
            }
            for (int e4 = tid; e4 < 128 * 26; e4 += 256) {
                int k = e4 / 26, u = e4 - k * 26;
                int n4 = u * 4, kg = cc * 128 + k;
                if (u < 25 && kg < 400)
                    cp16(smb + (uint32_t)((W3S + k * 136 + n4) * 4), W3a + kg * 100 + n4);
                else
                    *(float4*)&sm[W3S + k * 136 + n4] = make_float4(0.f, 0.f, 0.f, 0.f);
            }
            asm volatile("cp.async.commit_group;");
            asm volatile("cp.async.wait_group 0;" ::: "memory");
            __syncthreads();
        }
    }

    // ---- L4 via mma: pred = relu(h3 + b3) @ W4 ----
    float h4[4] = {0.f, 0.f, 0.f, 0.f};
    #pragma unroll
    for (int j = 0; j < 13; j++) {
        int col = j * 8 + 2 * t4;
        float ba = sm[B3S + col], bb = sm[B3S + col + 1];
        float e0[4];
        e0[0] = to_tf32_f(fmaxf(h3acc[j][0] + ba, 0.f));
        e0[1] = to_tf32_f(fmaxf(h3acc[j][1] + bb, 0.f));
        e0[2] = to_tf32_f(fmaxf(h3acc[j][2] + ba, 0.f));
        e0[3] = to_tf32_f(fmaxf(h3acc[j][3] + bb, 0.f));
        uint32_t f[4];
        cfrag_to_afrag(e0, f, t4);
        uint32_t b0 = __float_as_uint(sm[W4B + (j * 8 + t4) * 8 + g]);
        uint32_t b1 = __float_as_uint(sm[W4B + (j * 8 + t4 + 4) * 8 + g]);
        mma_tf32(h4, f, b0, b1);
    }
    {
        int m0 = 2 * t4;
        if (m0 < 6) {
            sm[PRED + (row0 + g) * 6 + m0]         = h4[0] + sm[B4S + m0];
            sm[PRED + (row0 + g + 8) * 6 + m0]     = h4[2] + sm[B4S + m0];
            sm[PRED + (row0 + g) * 6 + m0 + 1]     = h4[1] + sm[B4S + m0 + 1];
            sm[PRED + (row0 + g + 8) * 6 + m0 + 1] = h4[3] + sm[B4S + m0 + 1];
        }
    }
    __syncthreads();

    // ---- scatter: ordered stores, last j wins ----
    if (tid < nrows) {
        int row = g_rowlist[pos0 + tid];
        int ptr = g_ptr[row];
        float* orow = out + (size_t)row * XDIM;
        int idx[6];
        idx[0] = 0;
        idx[1] = ptr;
        idx[2] = clampi(ptr - GS);
        idx[3] = clampi(ptr + GS);
        idx[4] = clampi(ptr - 1);
        idx[5] = clampi(ptr + 1);
        #pragma unroll 1
        for (int j = 0; j < 6; j++)
            orow[idx[j]] = sm[ATT + tid * 6 + j] + sm[PRED + tid * 6 + j];
    }
}

// ---------------- launch ----------------
extern "C" void kernel_launch(void* const* d_in, const int* in_sizes, int n_in,
                              void* d_out, int out_size) {
    const float* x  = (const float*)d_in[0];
    const float* W1 = (const float*)d_in[1];
    const float* b1 = (const float*)d_in[2];
    const float* W2 = (const float*)d_in[3];
    const float* b2 = (const float*)d_in[4];
    const float* W3 = (const float*)d_in[5];
    const float* b3 = (const float*)d_in[6];
    const float* W4 = (const float*)d_in[7];
    const float* b4 = (const float*)d_in[8];
    const int*  act = (const int*)d_in[9];
    float* out = (float*)d_out;

    cudaFuncSetAttribute(fused_k, cudaFuncAttributeMaxDynamicSharedMemorySize, SMEM_BYTES);

    zero_k<<<1, 32>>>();
    prep_k<<<BATCH / 8, 256>>>(x, act, out);
    compact_k<<<BATCH / 256, 256>>>(act);
    fused_k<<<BATCH / TM + 3, 256, SMEM_BYTES>>>(W1, b1, W2, b2, W3, b3, W4, b4, out);
}